// round 13
// baseline (speedup 1.0000x reference)
#include <cuda_runtime.h>
#include <cuda_bf16.h>
#include <mma.h>
#include <cstdint>

using namespace nvcuda;
using bf16 = __nv_bfloat16;

// ---------------- scratch (device globals; no allocs) ----------------
__device__ bf16  g_poolh[320 * 25088];
__device__ bf16  g_pooll[320 * 25088];
__device__ bf16  g_W1h[25088 * 4096];
__device__ bf16  g_W1l[25088 * 4096];
__device__ bf16  g_W2h[4096 * 4096];
__device__ bf16  g_W2l[4096 * 4096];
__device__ bf16  g_fc6h[320 * 4096];
__device__ bf16  g_fc6l[320 * 4096];
__device__ float g_fc7[320 * 4096];
__device__ float g_part[4 * 320 * 4096];

__device__ __forceinline__ uint32_t pack_hi(float f0, float f1) {
    uint32_t r;
    asm("cvt.rn.bf16x2.f32 %0, %1, %2;" : "=r"(r) : "f"(f1), "f"(f0));  // low=bf16(f0)
    return r;
}
__device__ __forceinline__ void cpa16(uint32_t dst, const void* src) {
    asm volatile("cp.async.cg.shared.global [%0], [%1], 16;" :: "r"(dst), "l"(src) : "memory");
}
__device__ __forceinline__ void cpa_commit() { asm volatile("cp.async.commit_group;" ::: "memory"); }
template <int N> __device__ __forceinline__ void cpa_wait() {
    asm volatile("cp.async.wait_group %0;" :: "n"(N) : "memory");
}

// ---------------- weight fp32 -> bf16 hi/lo planes ----------------
__global__ void convW_kernel(const float* __restrict__ W, bf16* __restrict__ Wh,
                             bf16* __restrict__ Wl, int n4) {
    int i = blockIdx.x * 256 + threadIdx.x;
    if (i >= n4) return;
    float4 w = ((const float4*)W)[i];
    uint32_t h01 = pack_hi(w.x, w.y), h23 = pack_hi(w.z, w.w);
    float l0 = w.x - __uint_as_float(h01 << 16);
    float l1 = w.y - __uint_as_float(h01 & 0xFFFF0000u);
    float l2 = w.z - __uint_as_float(h23 << 16);
    float l3 = w.w - __uint_as_float(h23 & 0xFFFF0000u);
    ((uint2*)Wh)[i] = make_uint2(h01, h23);
    ((uint2*)Wl)[i] = make_uint2(pack_hi(l0, l1), pack_hi(l2, l3));
}

// ---------------- ROI max pool -> bf16 hi/lo planes ----------------
__global__ void roipool_kernel(const float* __restrict__ x, const float* __restrict__ rois,
                               const int* __restrict__ ridx) {
    int m = blockIdx.x, cg = blockIdx.y;
    size_t ob = (size_t)m * 25088 + (size_t)cg * 128 * 49;
    if (m >= 300) {
        for (int u = threadIdx.x; u < 128 * 49; u += 256) {
            g_poolh[ob + u] = __float2bfloat16_rn(0.f);
            g_pooll[ob + u] = __float2bfloat16_rn(0.f);
        }
        return;
    }
    float y1 = rois[m * 4 + 0], x1 = rois[m * 4 + 1];
    float y2 = rois[m * 4 + 2], x2 = rois[m * 4 + 3];
    int bi = ridx[m];
    int sh_ = (int)rintf(y1 * 0.0625f), sw_ = (int)rintf(x1 * 0.0625f);
    int eh_ = (int)rintf(y2 * 0.0625f), ew_ = (int)rintf(x2 * 0.0625f);
    const float INV7 = 1.0f / 7.0f;   // XLA reciprocal-multiply; bit-exact match required
    float bh = fmaxf((float)(eh_ - sh_ + 1), 1.f) * INV7;
    float bw = fmaxf((float)(ew_ - sw_ + 1), 1.f) * INV7;
    const float* fm = x + (size_t)bi * 512 * 1900;
    for (int u = threadIdx.x; u < 1568; u += 256) {
        int bin = u % 49, cq = u / 49;
        int ph = bin / 7, pw = bin % 7;
        int hs = min(max((int)floorf((float)ph * bh) + sh_, 0), 38);
        int he = min(max((int)ceilf((float)(ph + 1) * bh) + sh_, 0), 38);
        int ws = min(max((int)floorf((float)pw * bw) + sw_, 0), 50);
        int we = min(max((int)ceilf((float)(pw + 1) * bw) + sw_, 0), 50);
        int c = cg * 128 + cq * 4;
        const float* f0 = fm + (size_t)c * 1900;
        float m0 = -1e30f, m1 = -1e30f, m2 = -1e30f, m3 = -1e30f;
        for (int y = hs; y < he; y++)
            for (int xx = ws; xx < we; xx++) {
                int idx = y * 50 + xx;
                m0 = fmaxf(m0, f0[idx]);
                m1 = fmaxf(m1, f0[idx + 1900]);
                m2 = fmaxf(m2, f0[idx + 3800]);
                m3 = fmaxf(m3, f0[idx + 5700]);
            }
        bool ok = (he > hs) && (we > ws);
        float v[4] = { ok ? m0 : 0.f, ok ? m1 : 0.f, ok ? m2 : 0.f, ok ? m3 : 0.f };
#pragma unroll
        for (int i = 0; i < 4; i++) {
            bf16 h = __float2bfloat16_rn(v[i]);
            g_poolh[ob + (cq * 4 + i) * 49 + bin] = h;
            g_pooll[ob + (cq * 4 + i) * 49 + bin] = __float2bfloat16_rn(v[i] - __bfloat162float(h));
        }
    }
}

// ---------------- split-bf16 wmma GEMM: 64x32 warp tiles ----------------
// Grid (bm=5 FASTEST, n0=32, ks): bm-sibling CTAs get adjacent block IDs so the
// 5 CTAs sharing a B tile are co-resident in the same wave -> B reads hit L2.
#define A_LD 40
#define B_LD 136
#define A_PLANE (64 * A_LD)     // 2560 elems per plane
#define B_PLANE (32 * B_LD)     // 4352
#define STAGE_ELEMS (2 * A_PLANE + 2 * B_PLANE)   // 13824 elems
#define STAGE_BYTES (STAGE_ELEMS * 2)             // 27648 B
#define NSTAGE 2

__global__ void __launch_bounds__(128, 4) gemm_wmma_kernel(
        const bf16* __restrict__ Ah, const bf16* __restrict__ Al,
        const bf16* __restrict__ Bh, const bf16* __restrict__ Bl,
        float* __restrict__ part, int K, int Kper) {
    extern __shared__ char smraw[];
    bf16* sm = (bf16*)smraw;
    uint32_t smb = (uint32_t)__cvta_generic_to_shared(smraw);

    int tid = threadIdx.x, wn = tid >> 5;         // 4 warps, each owns n-slice of 32
    int bm = blockIdx.x * 64, n0 = blockIdx.y * 128;   // bm fastest for B-tile L2 reuse
    int kbase = blockIdx.z * Kper;
    float* C = part + (size_t)blockIdx.z * 320 * 4096;

    wmma::fragment<wmma::accumulator, 16, 16, 16, float> acc[4][2];
#pragma unroll
    for (int i = 0; i < 4; i++)
#pragma unroll
        for (int j = 0; j < 2; j++) wmma::fill_fragment(acc[i][j], 0.f);

#define LOADCPY(buf, kc0)                                                              \
    do {                                                                               \
        uint32_t st = smb + (buf) * STAGE_BYTES;                                       \
        _Pragma("unroll")                                                              \
        for (int it = 0; it < 2; it++) {                                               \
            int idx = it * 128 + tid;                                                  \
            int row = idx >> 2, q = idx & 3;                                           \
            size_t aoff = (size_t)(bm + row) * K + (kc0) + q * 8;                      \
            cpa16(st + (row * A_LD + q * 8) * 2, Ah + aoff);                           \
            cpa16(st + ((64 + row) * A_LD + q * 8) * 2, Al + aoff);                    \
        }                                                                              \
        uint32_t sb = st + 2 * A_PLANE * 2;                                            \
        _Pragma("unroll")                                                              \
        for (int it = 0; it < 4; it++) {                                               \
            int idx = it * 128 + tid;                                                  \
            int row = idx >> 4, nq = idx & 15;                                         \
            size_t boff = (size_t)((kc0) + row) * 4096 + n0 + nq * 8;                  \
            cpa16(sb + (row * B_LD + nq * 8) * 2, Bh + boff);                          \
            cpa16(sb + ((32 + row) * B_LD + nq * 8) * 2, Bl + boff);                   \
        }                                                                              \
        cpa_commit();                                                                  \
    } while (0)

    int nk = Kper >> 5;
    LOADCPY(0, kbase);
    for (int kt = 0; kt < nk; kt++) {
        int buf = kt & 1;
        if (kt + 1 < nk) { LOADCPY(buf ^ 1, kbase + ((kt + 1) << 5)); cpa_wait<1>(); }
        else             { cpa_wait<0>(); }
        __syncthreads();

        const bf16* st = sm + buf * STAGE_ELEMS;
        const bf16* Ahs = st;
        const bf16* Als = st + A_PLANE;
        const bf16* Bhs = st + 2 * A_PLANE;
        const bf16* Bls = Bhs + B_PLANE;
#pragma unroll
        for (int ks = 0; ks < 2; ks++) {
            wmma::fragment<wmma::matrix_b, 16, 16, 16, bf16, wmma::row_major> b_hi[2], b_lo[2];
#pragma unroll
            for (int j = 0; j < 2; j++) {
                wmma::load_matrix_sync(b_hi[j], Bhs + (ks * 16) * B_LD + wn * 32 + j * 16, B_LD);
                wmma::load_matrix_sync(b_lo[j], Bls + (ks * 16) * B_LD + wn * 32 + j * 16, B_LD);
            }
#pragma unroll
            for (int i = 0; i < 4; i++) {
                wmma::fragment<wmma::matrix_a, 16, 16, 16, bf16, wmma::row_major> a_hi, a_lo;
                wmma::load_matrix_sync(a_hi, Ahs + (i * 16) * A_LD + ks * 16, A_LD);
                wmma::load_matrix_sync(a_lo, Als + (i * 16) * A_LD + ks * 16, A_LD);
#pragma unroll
                for (int j = 0; j < 2; j++) {
                    wmma::mma_sync(acc[i][j], a_hi, b_hi[j], acc[i][j]);
                    wmma::mma_sync(acc[i][j], a_hi, b_lo[j], acc[i][j]);
                    wmma::mma_sync(acc[i][j], a_lo, b_hi[j], acc[i][j]);
                }
            }
        }
        __syncthreads();
    }
#pragma unroll
    for (int i = 0; i < 4; i++)
#pragma unroll
        for (int j = 0; j < 2; j++)
            wmma::store_matrix_sync(C + (size_t)(bm + i * 16) * 4096 + n0 + wn * 32 + j * 16,
                                    acc[i][j], 4096, wmma::mem_row_major);
#undef LOADCPY
}

// ---------------- reduce K-split(4) + bias + relu ----------------
__global__ void reduce_planes_kernel(const float* __restrict__ p, const float* __restrict__ bias,
                                     bf16* __restrict__ oh, bf16* __restrict__ ol) {
    int i = blockIdx.x * 256 + threadIdx.x;
    float v = (p[i] + p[i + 1310720]) + (p[i + 2621440] + p[i + 3932160]) + bias[i & 4095];
    v = fmaxf(v, 0.f);
    bf16 h = __float2bfloat16_rn(v);
    oh[i] = h;
    ol[i] = __float2bfloat16_rn(v - __bfloat162float(h));
}
__global__ void reduce_f32_kernel(const float* __restrict__ p, const float* __restrict__ bias,
                                  float* __restrict__ o) {
    int i = blockIdx.x * 256 + threadIdx.x;
    float v = (p[i] + p[i + 1310720]) + (p[i + 2621440] + p[i + 3932160]) + bias[i & 4095];
    o[i] = fmaxf(v, 0.f);
}

// ---------------- head: 4 rows per block ----------------
__global__ void __launch_bounds__(128) head4_kernel(const float* __restrict__ fc7,
                                                    const float* __restrict__ Ws,
                                                    const float* __restrict__ bs,
                                                    const float* __restrict__ Wp,
                                                    const float* __restrict__ bp,
                                                    float* __restrict__ out) {
    extern __shared__ float s[];
    int r0 = blockIdx.x * 4;
    const float4* src = (const float4*)(fc7 + (size_t)r0 * 4096);
    for (int i = threadIdx.x; i < 4096; i += 128) ((float4*)s)[i] = src[i];
    __syncthreads();
    int c = threadIdx.x;
    if (c >= 105) return;
    const float* W;
    int stride;
    float bias;
    if (c < 84) { W = Wp + c; stride = 84; bias = bp[c]; }
    else        { W = Ws + (c - 84); stride = 21; bias = bs[c - 84]; }
    float a0 = 0.f, a1 = 0.f, a2 = 0.f, a3 = 0.f;
#pragma unroll 4
    for (int k = 0; k < 4096; k++) {
        float w = W[(size_t)k * stride];
        a0 = fmaf(s[k], w, a0);
        a1 = fmaf(s[4096 + k], w, a1);
        a2 = fmaf(s[8192 + k], w, a2);
        a3 = fmaf(s[12288 + k], w, a3);
    }
    if (c < 84) {
        out[(r0 + 0) * 84 + c] = a0 + bias;
        out[(r0 + 1) * 84 + c] = a1 + bias;
        out[(r0 + 2) * 84 + c] = a2 + bias;
        out[(r0 + 3) * 84 + c] = a3 + bias;
    } else {
        int cc = c - 84;
        out[25200 + (r0 + 0) * 21 + cc] = a0 + bias;
        out[25200 + (r0 + 1) * 21 + cc] = a1 + bias;
        out[25200 + (r0 + 2) * 21 + cc] = a2 + bias;
        out[25200 + (r0 + 3) * 21 + cc] = a3 + bias;
    }
}

// ---------------- launch ----------------
extern "C" void kernel_launch(void* const* d_in, const int* in_sizes, int n_in,
                              void* d_out, int out_size) {
    const float* x    = (const float*)d_in[0];
    const float* rois = (const float*)d_in[1];
    const int*   ridx = (const int*)d_in[2];
    const float* W1   = (const float*)d_in[3];
    const float* b1   = (const float*)d_in[4];
    const float* W2   = (const float*)d_in[5];
    const float* b2   = (const float*)d_in[6];
    const float* Ws   = (const float*)d_in[7];
    const float* bs   = (const float*)d_in[8];
    const float* Wp   = (const float*)d_in[9];
    const float* bp   = (const float*)d_in[10];
    float* out = (float*)d_out;

    void *pPh, *pPl, *pW1h, *pW1l, *pW2h, *pW2l, *pF6h, *pF6l, *pF7, *pPart;
    cudaGetSymbolAddress(&pPh, g_poolh);   cudaGetSymbolAddress(&pPl, g_pooll);
    cudaGetSymbolAddress(&pW1h, g_W1h);    cudaGetSymbolAddress(&pW1l, g_W1l);
    cudaGetSymbolAddress(&pW2h, g_W2h);    cudaGetSymbolAddress(&pW2l, g_W2l);
    cudaGetSymbolAddress(&pF6h, g_fc6h);   cudaGetSymbolAddress(&pF6l, g_fc6l);
    cudaGetSymbolAddress(&pF7, g_fc7);     cudaGetSymbolAddress(&pPart, g_part);

    const int GEMM_SMEM = STAGE_BYTES * NSTAGE;   // 55,296 bytes
    cudaFuncSetAttribute(gemm_wmma_kernel, cudaFuncAttributeMaxDynamicSharedMemorySize, GEMM_SMEM);
    cudaFuncSetAttribute(head4_kernel, cudaFuncAttributeMaxDynamicSharedMemorySize, 65536);

    convW_kernel<<<(25088 * 4096 / 4) / 256, 256>>>(W1, (bf16*)pW1h, (bf16*)pW1l, 25088 * 4096 / 4);
    convW_kernel<<<(4096 * 4096 / 4) / 256, 256>>>(W2, (bf16*)pW2h, (bf16*)pW2l, 4096 * 4096 / 4);
    roipool_kernel<<<dim3(320, 4), 256>>>(x, rois, ridx);

    gemm_wmma_kernel<<<dim3(5, 32, 4), 128, GEMM_SMEM>>>(
        (const bf16*)pPh, (const bf16*)pPl, (const bf16*)pW1h, (const bf16*)pW1l,
        (float*)pPart, 25088, 6272);
    reduce_planes_kernel<<<5120, 256>>>((const float*)pPart, b1, (bf16*)pF6h, (bf16*)pF6l);

    gemm_wmma_kernel<<<dim3(5, 32, 4), 128, GEMM_SMEM>>>(
        (const bf16*)pF6h, (const bf16*)pF6l, (const bf16*)pW2h, (const bf16*)pW2l,
        (float*)pPart, 4096, 1024);
    reduce_f32_kernel<<<5120, 256>>>((const float*)pPart, b2, (float*)pF7);

    head4_kernel<<<75, 128, 65536>>>((const float*)pF7, Ws, bs, Wp, bp, out);
}

// round 14
// speedup vs baseline: 1.1023x; 1.1023x over previous
#include <cuda_runtime.h>
#include <cuda_bf16.h>
#include <mma.h>
#include <cstdint>

using namespace nvcuda;
using bf16 = __nv_bfloat16;

// ---------------- scratch (device globals; no allocs) ----------------
__device__ bf16  g_poolh[320 * 25088];
__device__ bf16  g_pooll[320 * 25088];
__device__ bf16  g_W1h[25088 * 4096];
__device__ bf16  g_W1l[25088 * 4096];
__device__ bf16  g_W2h[4096 * 4096];
__device__ bf16  g_W2l[4096 * 4096];
__device__ bf16  g_fc6h[320 * 4096];
__device__ bf16  g_fc6l[320 * 4096];
__device__ float g_fc7[320 * 4096];
__device__ float g_part[16 * 320 * 4096];

__device__ __forceinline__ uint32_t pack_hi(float f0, float f1) {
    uint32_t r;
    asm("cvt.rn.bf16x2.f32 %0, %1, %2;" : "=r"(r) : "f"(f1), "f"(f0));  // low=bf16(f0)
    return r;
}
__device__ __forceinline__ void cpa16(uint32_t dst, const void* src) {
    asm volatile("cp.async.cg.shared.global [%0], [%1], 16;" :: "r"(dst), "l"(src) : "memory");
}
__device__ __forceinline__ void cpa_commit() { asm volatile("cp.async.commit_group;" ::: "memory"); }
template <int N> __device__ __forceinline__ void cpa_wait() {
    asm volatile("cp.async.wait_group %0;" :: "n"(N) : "memory");
}

// ---------------- weight fp32 -> bf16 hi/lo planes ----------------
__global__ void convW_kernel(const float* __restrict__ W, bf16* __restrict__ Wh,
                             bf16* __restrict__ Wl, int n4) {
    int i = blockIdx.x * 256 + threadIdx.x;
    if (i >= n4) return;
    float4 w = ((const float4*)W)[i];
    uint32_t h01 = pack_hi(w.x, w.y), h23 = pack_hi(w.z, w.w);
    float l0 = w.x - __uint_as_float(h01 << 16);
    float l1 = w.y - __uint_as_float(h01 & 0xFFFF0000u);
    float l2 = w.z - __uint_as_float(h23 << 16);
    float l3 = w.w - __uint_as_float(h23 & 0xFFFF0000u);
    ((uint2*)Wh)[i] = make_uint2(h01, h23);
    ((uint2*)Wl)[i] = make_uint2(pack_hi(l0, l1), pack_hi(l2, l3));
}

// ---------------- ROI max pool -> bf16 hi/lo planes ----------------
__global__ void roipool_kernel(const float* __restrict__ x, const float* __restrict__ rois,
                               const int* __restrict__ ridx) {
    int m = blockIdx.x, cg = blockIdx.y;
    size_t ob = (size_t)m * 25088 + (size_t)cg * 128 * 49;
    if (m >= 300) {
        for (int u = threadIdx.x; u < 128 * 49; u += 256) {
            g_poolh[ob + u] = __float2bfloat16_rn(0.f);
            g_pooll[ob + u] = __float2bfloat16_rn(0.f);
        }
        return;
    }
    float y1 = rois[m * 4 + 0], x1 = rois[m * 4 + 1];
    float y2 = rois[m * 4 + 2], x2 = rois[m * 4 + 3];
    int bi = ridx[m];
    int sh_ = (int)rintf(y1 * 0.0625f), sw_ = (int)rintf(x1 * 0.0625f);
    int eh_ = (int)rintf(y2 * 0.0625f), ew_ = (int)rintf(x2 * 0.0625f);
    const float INV7 = 1.0f / 7.0f;   // XLA reciprocal-multiply; bit-exact match required
    float bh = fmaxf((float)(eh_ - sh_ + 1), 1.f) * INV7;
    float bw = fmaxf((float)(ew_ - sw_ + 1), 1.f) * INV7;
    const float* fm = x + (size_t)bi * 512 * 1900;
    for (int u = threadIdx.x; u < 1568; u += 256) {
        int bin = u % 49, cq = u / 49;
        int ph = bin / 7, pw = bin % 7;
        int hs = min(max((int)floorf((float)ph * bh) + sh_, 0), 38);
        int he = min(max((int)ceilf((float)(ph + 1) * bh) + sh_, 0), 38);
        int ws = min(max((int)floorf((float)pw * bw) + sw_, 0), 50);
        int we = min(max((int)ceilf((float)(pw + 1) * bw) + sw_, 0), 50);
        int c = cg * 128 + cq * 4;
        const float* f0 = fm + (size_t)c * 1900;
        float m0 = -1e30f, m1 = -1e30f, m2 = -1e30f, m3 = -1e30f;
        for (int y = hs; y < he; y++)
            for (int xx = ws; xx < we; xx++) {
                int idx = y * 50 + xx;
                m0 = fmaxf(m0, f0[idx]);
                m1 = fmaxf(m1, f0[idx + 1900]);
                m2 = fmaxf(m2, f0[idx + 3800]);
                m3 = fmaxf(m3, f0[idx + 5700]);
            }
        bool ok = (he > hs) && (we > ws);
        float v[4] = { ok ? m0 : 0.f, ok ? m1 : 0.f, ok ? m2 : 0.f, ok ? m3 : 0.f };
#pragma unroll
        for (int i = 0; i < 4; i++) {
            bf16 h = __float2bfloat16_rn(v[i]);
            g_poolh[ob + (cq * 4 + i) * 49 + bin] = h;
            g_pooll[ob + (cq * 4 + i) * 49 + bin] = __float2bfloat16_rn(v[i] - __bfloat162float(h));
        }
    }
}

// ---------------- split-bf16 wmma GEMM: 64x32 warp tiles, K-split 16 ----------------
#define A_LD 40
#define B_LD 136
#define A_PLANE (64 * A_LD)     // 2560 elems per plane
#define B_PLANE (32 * B_LD)     // 4352
#define STAGE_ELEMS (2 * A_PLANE + 2 * B_PLANE)   // 13824 elems
#define STAGE_BYTES (STAGE_ELEMS * 2)             // 27648 B
#define NSTAGE 2

__global__ void __launch_bounds__(128, 4) gemm_wmma_kernel(
        const bf16* __restrict__ Ah, const bf16* __restrict__ Al,
        const bf16* __restrict__ Bh, const bf16* __restrict__ Bl,
        float* __restrict__ part, int K, int Kper) {
    extern __shared__ char smraw[];
    bf16* sm = (bf16*)smraw;
    uint32_t smb = (uint32_t)__cvta_generic_to_shared(smraw);

    int tid = threadIdx.x, wn = tid >> 5;         // 4 warps, each owns n-slice of 32
    int n0 = blockIdx.x * 128, bm = blockIdx.y * 64;
    int kbase = blockIdx.z * Kper;
    float* C = part + (size_t)blockIdx.z * 320 * 4096;

    wmma::fragment<wmma::accumulator, 16, 16, 16, float> acc[4][2];
#pragma unroll
    for (int i = 0; i < 4; i++)
#pragma unroll
        for (int j = 0; j < 2; j++) wmma::fill_fragment(acc[i][j], 0.f);

#define LOADCPY(buf, kc0)                                                              \
    do {                                                                               \
        uint32_t st = smb + (buf) * STAGE_BYTES;                                       \
        _Pragma("unroll")                                                              \
        for (int it = 0; it < 2; it++) {                                               \
            int idx = it * 128 + tid;                                                  \
            int row = idx >> 2, q = idx & 3;                                           \
            size_t aoff = (size_t)(bm + row) * K + (kc0) + q * 8;                      \
            cpa16(st + (row * A_LD + q * 8) * 2, Ah + aoff);                           \
            cpa16(st + ((64 + row) * A_LD + q * 8) * 2, Al + aoff);                    \
        }                                                                              \
        uint32_t sb = st + 2 * A_PLANE * 2;                                            \
        _Pragma("unroll")                                                              \
        for (int it = 0; it < 4; it++) {                                               \
            int idx = it * 128 + tid;                                                  \
            int row = idx >> 4, nq = idx & 15;                                         \
            size_t boff = (size_t)((kc0) + row) * 4096 + n0 + nq * 8;                  \
            cpa16(sb + (row * B_LD + nq * 8) * 2, Bh + boff);                          \
            cpa16(sb + ((32 + row) * B_LD + nq * 8) * 2, Bl + boff);                   \
        }                                                                              \
        cpa_commit();                                                                  \
    } while (0)

    int nk = Kper >> 5;
    LOADCPY(0, kbase);
    for (int kt = 0; kt < nk; kt++) {
        int buf = kt & 1;
        if (kt + 1 < nk) { LOADCPY(buf ^ 1, kbase + ((kt + 1) << 5)); cpa_wait<1>(); }
        else             { cpa_wait<0>(); }
        __syncthreads();

        const bf16* st = sm + buf * STAGE_ELEMS;
        const bf16* Ahs = st;
        const bf16* Als = st + A_PLANE;
        const bf16* Bhs = st + 2 * A_PLANE;
        const bf16* Bls = Bhs + B_PLANE;
#pragma unroll
        for (int ks = 0; ks < 2; ks++) {
            wmma::fragment<wmma::matrix_b, 16, 16, 16, bf16, wmma::row_major> b_hi[2], b_lo[2];
#pragma unroll
            for (int j = 0; j < 2; j++) {
                wmma::load_matrix_sync(b_hi[j], Bhs + (ks * 16) * B_LD + wn * 32 + j * 16, B_LD);
                wmma::load_matrix_sync(b_lo[j], Bls + (ks * 16) * B_LD + wn * 32 + j * 16, B_LD);
            }
#pragma unroll
            for (int i = 0; i < 4; i++) {
                wmma::fragment<wmma::matrix_a, 16, 16, 16, bf16, wmma::row_major> a_hi, a_lo;
                wmma::load_matrix_sync(a_hi, Ahs + (i * 16) * A_LD + ks * 16, A_LD);
                wmma::load_matrix_sync(a_lo, Als + (i * 16) * A_LD + ks * 16, A_LD);
#pragma unroll
                for (int j = 0; j < 2; j++) {
                    wmma::mma_sync(acc[i][j], a_hi, b_hi[j], acc[i][j]);
                    wmma::mma_sync(acc[i][j], a_hi, b_lo[j], acc[i][j]);
                    wmma::mma_sync(acc[i][j], a_lo, b_hi[j], acc[i][j]);
                }
            }
        }
        __syncthreads();
    }
#pragma unroll
    for (int i = 0; i < 4; i++)
#pragma unroll
        for (int j = 0; j < 2; j++)
            wmma::store_matrix_sync(C + (size_t)(bm + i * 16) * 4096 + n0 + wn * 32 + j * 16,
                                    acc[i][j], 4096, wmma::mem_row_major);
#undef LOADCPY
}

// ---------------- reduce K-split(16) + bias + relu ----------------
#define PART_STRIDE 1310720   // 320*4096
__global__ void reduce_planes_kernel(const float* __restrict__ p, const float* __restrict__ bias,
                                     bf16* __restrict__ oh, bf16* __restrict__ ol) {
    int i = blockIdx.x * 256 + threadIdx.x;
    float v = bias[i & 4095];
#pragma unroll
    for (int z = 0; z < 16; z++) v += p[i + (size_t)z * PART_STRIDE];
    v = fmaxf(v, 0.f);
    bf16 h = __float2bfloat16_rn(v);
    oh[i] = h;
    ol[i] = __float2bfloat16_rn(v - __bfloat162float(h));
}
__global__ void reduce_f32_kernel(const float* __restrict__ p, const float* __restrict__ bias,
                                  float* __restrict__ o) {
    int i = blockIdx.x * 256 + threadIdx.x;
    float v = bias[i & 4095];
#pragma unroll
    for (int z = 0; z < 16; z++) v += p[i + (size_t)z * PART_STRIDE];
    o[i] = fmaxf(v, 0.f);
}

// ---------------- head: 4 rows per block ----------------
__global__ void __launch_bounds__(128) head4_kernel(const float* __restrict__ fc7,
                                                    const float* __restrict__ Ws,
                                                    const float* __restrict__ bs,
                                                    const float* __restrict__ Wp,
                                                    const float* __restrict__ bp,
                                                    float* __restrict__ out) {
    extern __shared__ float s[];
    int r0 = blockIdx.x * 4;
    const float4* src = (const float4*)(fc7 + (size_t)r0 * 4096);
    for (int i = threadIdx.x; i < 4096; i += 128) ((float4*)s)[i] = src[i];
    __syncthreads();
    int c = threadIdx.x;
    if (c >= 105) return;
    const float* W;
    int stride;
    float bias;
    if (c < 84) { W = Wp + c; stride = 84; bias = bp[c]; }
    else        { W = Ws + (c - 84); stride = 21; bias = bs[c - 84]; }
    float a0 = 0.f, a1 = 0.f, a2 = 0.f, a3 = 0.f;
#pragma unroll 4
    for (int k = 0; k < 4096; k++) {
        float w = W[(size_t)k * stride];
        a0 = fmaf(s[k], w, a0);
        a1 = fmaf(s[4096 + k], w, a1);
        a2 = fmaf(s[8192 + k], w, a2);
        a3 = fmaf(s[12288 + k], w, a3);
    }
    if (c < 84) {
        out[(r0 + 0) * 84 + c] = a0 + bias;
        out[(r0 + 1) * 84 + c] = a1 + bias;
        out[(r0 + 2) * 84 + c] = a2 + bias;
        out[(r0 + 3) * 84 + c] = a3 + bias;
    } else {
        int cc = c - 84;
        out[25200 + (r0 + 0) * 21 + cc] = a0 + bias;
        out[25200 + (r0 + 1) * 21 + cc] = a1 + bias;
        out[25200 + (r0 + 2) * 21 + cc] = a2 + bias;
        out[25200 + (r0 + 3) * 21 + cc] = a3 + bias;
    }
}

// ---------------- launch ----------------
extern "C" void kernel_launch(void* const* d_in, const int* in_sizes, int n_in,
                              void* d_out, int out_size) {
    const float* x    = (const float*)d_in[0];
    const float* rois = (const float*)d_in[1];
    const int*   ridx = (const int*)d_in[2];
    const float* W1   = (const float*)d_in[3];
    const float* b1   = (const float*)d_in[4];
    const float* W2   = (const float*)d_in[5];
    const float* b2   = (const float*)d_in[6];
    const float* Ws   = (const float*)d_in[7];
    const float* bs   = (const float*)d_in[8];
    const float* Wp   = (const float*)d_in[9];
    const float* bp   = (const float*)d_in[10];
    float* out = (float*)d_out;

    void *pPh, *pPl, *pW1h, *pW1l, *pW2h, *pW2l, *pF6h, *pF6l, *pF7, *pPart;
    cudaGetSymbolAddress(&pPh, g_poolh);   cudaGetSymbolAddress(&pPl, g_pooll);
    cudaGetSymbolAddress(&pW1h, g_W1h);    cudaGetSymbolAddress(&pW1l, g_W1l);
    cudaGetSymbolAddress(&pW2h, g_W2h);    cudaGetSymbolAddress(&pW2l, g_W2l);
    cudaGetSymbolAddress(&pF6h, g_fc6h);   cudaGetSymbolAddress(&pF6l, g_fc6l);
    cudaGetSymbolAddress(&pF7, g_fc7);     cudaGetSymbolAddress(&pPart, g_part);

    const int GEMM_SMEM = STAGE_BYTES * NSTAGE;   // 55,296 bytes
    cudaFuncSetAttribute(gemm_wmma_kernel, cudaFuncAttributeMaxDynamicSharedMemorySize, GEMM_SMEM);
    cudaFuncSetAttribute(head4_kernel, cudaFuncAttributeMaxDynamicSharedMemorySize, 65536);

    convW_kernel<<<(25088 * 4096 / 4) / 256, 256>>>(W1, (bf16*)pW1h, (bf16*)pW1l, 25088 * 4096 / 4);
    convW_kernel<<<(4096 * 4096 / 4) / 256, 256>>>(W2, (bf16*)pW2h, (bf16*)pW2l, 4096 * 4096 / 4);
    roipool_kernel<<<dim3(320, 4), 256>>>(x, rois, ridx);

    gemm_wmma_kernel<<<dim3(32, 5, 16), 128, GEMM_SMEM>>>(
        (const bf16*)pPh, (const bf16*)pPl, (const bf16*)pW1h, (const bf16*)pW1l,
        (float*)pPart, 25088, 1568);
    reduce_planes_kernel<<<5120, 256>>>((const float*)pPart, b1, (bf16*)pF6h, (bf16*)pF6l);

    gemm_wmma_kernel<<<dim3(32, 5, 16), 128, GEMM_SMEM>>>(
        (const bf16*)pF6h, (const bf16*)pF6l, (const bf16*)pW2h, (const bf16*)pW2l,
        (float*)pPart, 4096, 256);
    reduce_f32_kernel<<<5120, 256>>>((const float*)pPart, b2, (float*)pF7);

    head4_kernel<<<75, 128, 65536>>>((const float*)pF7, Ws, bs, Wp, bp, out);
}